// round 4
// baseline (speedup 1.0000x reference)
#include <cuda_runtime.h>
#include <cuda_bf16.h>
#include <math.h>

// ---------------- problem constants ----------------
#define DIMF     128     // node / edge / out feature dim
#define DTIME    100
#define LDQ      228     // wq_w leading dim (128+100)
#define LDKV     356     // wk_w / wv_w leading dim (128+128+100)
#define LDOUT    256     // wout_w leading dim (128+128)
#define MAXD     25024
#define MAXE     250048
#define LN_EPS   1e-5f

// ---------------- device scratch (static, allocation-free) ----------------
__device__ float g_Q  [(size_t)MAXD * DIMF];
__device__ float g_K  [(size_t)MAXE * DIMF];
__device__ float g_V  [(size_t)MAXE * DIMF];
__device__ float g_h  [(size_t)MAXD * DIMF];
__device__ float g_rst[(size_t)MAXD * DIMF];
__device__ float g_qb2[DIMF];
__device__ int   g_nstart[MAXD + 2];

// ---------------- small precompute kernels ----------------

// qb2[o] = wq_b[o] + sum_t wq_w[o,128+t] * cos(time_b[t])
__global__ void qb2_kernel(const float* __restrict__ wq_w,
                           const float* __restrict__ wq_b,
                           const float* __restrict__ time_b) {
    int o = threadIdx.x;
    if (o >= DIMF) return;
    float s = wq_b[o];
    #pragma unroll 4
    for (int t = 0; t < DTIME; t++)
        s += wq_w[(size_t)o * LDQ + DIMF + t] * cosf(time_b[t]);
    g_qb2[o] = s;
}

// g_nstart[d] = lower_bound(edge_dst, d) for d in [0, D]
__global__ void nstart_kernel(const int* __restrict__ edge_dst, int E, int D) {
    int d = blockIdx.x * blockDim.x + threadIdx.x;
    if (d > D) return;
    int lo = 0, hi = E;
    while (lo < hi) {
        int mid = (lo + hi) >> 1;
        if (edge_dst[mid] < d) lo = mid + 1; else hi = mid;
    }
    g_nstart[d] = lo;
}

// ---------------- fused-gather SGEMM: C[M x 128] = A[M x K] @ W^T + bias ----------------
// MODE 0: Q proj    A(i,k) = src_feat[src_idx[i]*128 + k]                 (K=128, W ld=228, bias=g_qb2)
// MODE 1: K/V proj  A(i,k) = kv | edge_f | cos(dt*tw+tb) pieces           (K=356, W ld=356)
// MODE 2: out proj  A(i,k) = k<128 ? g_h[i,k] : src_feat[src_idx[i],k-128](K=256, W ld=256, +ReLU)

template<int MODE>
__device__ __forceinline__ float fetchA(int row, int k,
                                        const float* __restrict__ sf,
                                        const int* __restrict__ sidx,
                                        const float* __restrict__ ef,
                                        const float* __restrict__ edt,
                                        const float* __restrict__ tw,
                                        const float* __restrict__ tb,
                                        int rowbase) {
    if (MODE == 0) {
        return sf[(size_t)sidx[row] * DIMF + k];
    } else if (MODE == 1) {
        if (k < DIMF)        return sf[(size_t)sidx[rowbase + row] * DIMF + k];
        else if (k < 2*DIMF) return ef[(size_t)row * DIMF + (k - DIMF)];
        else {
            int t = k - 2*DIMF;
            return cosf(edt[row] * tw[t] + tb[t]);
        }
    } else {
        if (k < DIMF) return g_h[(size_t)row * DIMF + k];
        else          return sf[(size_t)sidx[row] * DIMF + (k - DIMF)];
    }
}

template<int MODE>
__global__ __launch_bounds__(256)
void gemm_tn(const float* __restrict__ W, int ldw, int ktot,
             const float* __restrict__ bias, int outsel, int M,
             const float* __restrict__ sf, const int* __restrict__ sidx,
             const float* __restrict__ ef, const float* __restrict__ edt,
             const float* __restrict__ tw, const float* __restrict__ tb,
             int rowbase) {
    __shared__ float As[16][132];
    __shared__ float Bs[16][132];

    float* out = (outsel == 0) ? g_Q : (outsel == 1) ? g_K : (outsel == 2) ? g_V : g_rst;

    const int tid = threadIdx.x;
    const int i0  = blockIdx.x * 128;
    const int lr  = tid >> 1;          // 0..127 (row within tile for loads)
    const int lk  = (tid & 1) * 8;     // 0 or 8
    const int tx  = tid & 15;          // output col group
    const int ty  = tid >> 4;          // output row group

    float acc[8][8];
    #pragma unroll
    for (int i = 0; i < 8; i++)
        #pragma unroll
        for (int j = 0; j < 8; j++) acc[i][j] = 0.f;

    for (int k0 = 0; k0 < ktot; k0 += 16) {
        // stage A tile (gather / generate)
        {
            int row = i0 + lr;
            #pragma unroll
            for (int j = 0; j < 8; j++) {
                int k = k0 + lk + j;
                float v = 0.f;
                if (row < M && k < ktot)
                    v = fetchA<MODE>(row, k, sf, sidx, ef, edt, tw, tb, rowbase);
                As[lk + j][lr] = v;
            }
        }
        // stage B tile (weights, transposed into smem)
        {
            #pragma unroll
            for (int j = 0; j < 8; j++) {
                int k = k0 + lk + j;
                Bs[lk + j][lr] = (k < ktot) ? W[(size_t)lr * ldw + k] : 0.f;
            }
        }
        __syncthreads();

        #pragma unroll
        for (int kk = 0; kk < 16; kk++) {
            float4 a0 = *(const float4*)&As[kk][ty * 8];
            float4 a1 = *(const float4*)&As[kk][ty * 8 + 4];
            float4 b0 = *(const float4*)&Bs[kk][tx * 8];
            float4 b1 = *(const float4*)&Bs[kk][tx * 8 + 4];
            float ar[8] = {a0.x, a0.y, a0.z, a0.w, a1.x, a1.y, a1.z, a1.w};
            float br[8] = {b0.x, b0.y, b0.z, b0.w, b1.x, b1.y, b1.z, b1.w};
            #pragma unroll
            for (int i = 0; i < 8; i++)
                #pragma unroll
                for (int j = 0; j < 8; j++)
                    acc[i][j] += ar[i] * br[j];
        }
        __syncthreads();
    }

    // epilogue
    #pragma unroll
    for (int i = 0; i < 8; i++) {
        int row = i0 + ty * 8 + i;
        if (row >= M) continue;
        #pragma unroll
        for (int j = 0; j < 8; j++) {
            int col = tx * 8 + j;
            float b = (MODE == 0) ? g_qb2[col] : bias[col];
            float v = acc[i][j] + b;
            if (MODE == 2) v = fmaxf(v, 0.f);
            out[(size_t)row * DIMF + col] = v;
        }
    }
}

// ---------------- per-destination online-softmax attention ----------------
// One warp per destination. lane l covers feature dims [4l, 4l+4); head = l>>2.
__global__ __launch_bounds__(256)
void attn_kernel(int D) {
    int w = (blockIdx.x * blockDim.x + threadIdx.x) >> 5;
    int lane = threadIdx.x & 31;
    if (w >= D) return;

    int s = g_nstart[w];
    int e = g_nstart[w + 1];

    float4 q = *(const float4*)&g_Q[(size_t)w * DIMF + lane * 4];

    float m = -3.402823466e38f;
    float den = 0.f;
    float4 acc = make_float4(0.f, 0.f, 0.f, 0.f);

    for (int i = s; i < e; i++) {
        float4 k4 = *(const float4*)&g_K[(size_t)i * DIMF + lane * 4];
        float dot = q.x * k4.x + q.y * k4.y + q.z * k4.z + q.w * k4.w;
        dot += __shfl_xor_sync(0xffffffffu, dot, 1);
        dot += __shfl_xor_sync(0xffffffffu, dot, 2);
        float sc = (dot > 0.f) ? dot : 0.2f * dot;     // leaky_relu(., 0.2)
        float nm = fmaxf(m, sc);
        float c  = expf(m - nm);                        // 0 on first iter
        float wt = expf(sc - nm);
        float4 v4 = *(const float4*)&g_V[(size_t)i * DIMF + lane * 4];
        acc.x = acc.x * c + wt * v4.x;
        acc.y = acc.y * c + wt * v4.y;
        acc.z = acc.z * c + wt * v4.z;
        acc.w = acc.w * c + wt * v4.w;
        den = den * c + wt;
        m = nm;
    }

    float inv = (e > s) ? 1.f / den : 0.f;
    float4 o = make_float4(acc.x * inv, acc.y * inv, acc.z * inv, acc.w * inv);
    *(float4*)&g_h[(size_t)w * DIMF + lane * 4] = o;
}

// ---------------- layernorm (warp per row) ----------------
__global__ __launch_bounds__(256)
void ln_kernel(const float* __restrict__ ln_g, const float* __restrict__ ln_b,
               float* __restrict__ out, int D) {
    int row = (blockIdx.x * blockDim.x + threadIdx.x) >> 5;
    int lane = threadIdx.x & 31;
    if (row >= D) return;

    float4 v = *(const float4*)&g_rst[(size_t)row * DIMF + lane * 4];
    float s  = v.x + v.y + v.z + v.w;
    float s2 = v.x * v.x + v.y * v.y + v.z * v.z + v.w * v.w;
    #pragma unroll
    for (int off = 16; off > 0; off >>= 1) {
        s  += __shfl_xor_sync(0xffffffffu, s,  off);
        s2 += __shfl_xor_sync(0xffffffffu, s2, off);
    }
    float mean = s * (1.f / DIMF);
    float var  = s2 * (1.f / DIMF) - mean * mean;
    float rstd = rsqrtf(var + LN_EPS);

    float4 g = *(const float4*)&ln_g[lane * 4];
    float4 b = *(const float4*)&ln_b[lane * 4];
    float4 o;
    o.x = (v.x - mean) * rstd * g.x + b.x;
    o.y = (v.y - mean) * rstd * g.y + b.y;
    o.z = (v.z - mean) * rstd * g.z + b.z;
    o.w = (v.w - mean) * rstd * g.w + b.w;
    *(float4*)&out[(size_t)row * DIMF + lane * 4] = o;
}

// ---------------- launcher ----------------
extern "C" void kernel_launch(void* const* d_in, const int* in_sizes, int n_in,
                              void* d_out, int out_size) {
    const float* src_feat = (const float*)d_in[0];
    const float* edge_f   = (const float*)d_in[1];
    const float* edge_dt  = (const float*)d_in[2];
    const float* time_w   = (const float*)d_in[3];
    const float* time_b   = (const float*)d_in[4];
    const float* wq_w     = (const float*)d_in[5];
    const float* wq_b     = (const float*)d_in[6];
    const float* wk_w     = (const float*)d_in[7];
    const float* wk_b     = (const float*)d_in[8];
    const float* wv_w     = (const float*)d_in[9];
    const float* wv_b     = (const float*)d_in[10];
    const float* wout_w   = (const float*)d_in[11];
    const float* wout_b   = (const float*)d_in[12];
    const float* ln_g     = (const float*)d_in[13];
    const float* ln_b     = (const float*)d_in[14];
    const int*   src_idx  = (const int*)d_in[15];   // JAX x64-disabled: int64 -> int32
    const int*   edge_dst = (const int*)d_in[16];   // JAX x64-disabled: int64 -> int32

    const int E = in_sizes[1] / DIMF;
    const int D = in_sizes[0] / DIMF - E;

    qb2_kernel<<<1, 128>>>(wq_w, wq_b, time_b);
    nstart_kernel<<<(D + 1 + 255) / 256, 256>>>(edge_dst, E, D);

    // Q projection: D x 128 = (node feats) @ wq_w[:, :128]^T + qb2
    gemm_tn<0><<<(D + 127) / 128, 256>>>(wq_w, LDQ, DIMF, wq_b, /*out*/0, D,
                                         src_feat, src_idx, edge_f, edge_dt,
                                         time_w, time_b, 0);
    // K projection
    gemm_tn<1><<<(E + 127) / 128, 256>>>(wk_w, LDKV, LDKV, wk_b, /*out*/1, E,
                                         src_feat, src_idx, edge_f, edge_dt,
                                         time_w, time_b, D);
    // V projection
    gemm_tn<1><<<(E + 127) / 128, 256>>>(wv_w, LDKV, LDKV, wv_b, /*out*/2, E,
                                         src_feat, src_idx, edge_f, edge_dt,
                                         time_w, time_b, D);

    attn_kernel<<<(D + 7) / 8, 256>>>(D);

    // output projection + ReLU into g_rst
    gemm_tn<2><<<(D + 127) / 128, 256>>>(wout_w, LDOUT, LDOUT, wout_b, /*out*/3, D,
                                         src_feat, src_idx, edge_f, edge_dt,
                                         time_w, time_b, 0);

    ln_kernel<<<(D + 7) / 8, 256>>>(ln_g, ln_b, (float*)d_out, D);
}

// round 7
// speedup vs baseline: 1.3352x; 1.3352x over previous
#include <cuda_runtime.h>
#include <cuda_bf16.h>
#include <math.h>
#include <stdint.h>

// ---------------- problem constants ----------------
#define DIMF     128
#define DTIME    100
#define LDQ      228
#define LDKV     356
#define LDOUT    256
#define MAXD     25024
#define MAXE     250048
#define LN_EPS   1e-5f

#define KPAD     384      // padded K for K/V projection (3 chunks of 128)
#define NCHUNK   3
#define ROWU32   68       // padded row stride in u32 (136 bf16) -> conflict-free frags

// ---------------- device scratch ----------------
__device__ float g_Q  [(size_t)MAXD * DIMF];
__device__ float g_K  [(size_t)MAXE * DIMF];
__device__ float g_V  [(size_t)MAXE * DIMF];
__device__ float g_h  [(size_t)MAXD * DIMF];
__device__ float g_rst[(size_t)MAXD * DIMF];
__device__ float g_qb2[DIMF];
__device__ int   g_nstart[MAXD + 2];
// pre-packed K/V weights, bf16 hi|lo, padded smem-identical layout:
// [part(hi,lo)][chunk][256 rows (K outs then V outs) * 17 uint4]
__device__ uint4 g_W2[2][NCHUNK][256 * (ROWU32 / 4)];

// ---------------- small precompute kernels ----------------
__global__ void qb2_kernel(const float* __restrict__ wq_w,
                           const float* __restrict__ wq_b,
                           const float* __restrict__ time_b) {
    int o = threadIdx.x;
    if (o >= DIMF) return;
    float s = wq_b[o];
    #pragma unroll 4
    for (int t = 0; t < DTIME; t++)
        s += wq_w[(size_t)o * LDQ + DIMF + t] * cosf(time_b[t]);
    g_qb2[o] = s;
}

__global__ void nstart_kernel(const int* __restrict__ edge_dst, int E, int D) {
    int d = blockIdx.x * blockDim.x + threadIdx.x;
    if (d > D) return;
    int lo = 0, hi = E;
    while (lo < hi) {
        int mid = (lo + hi) >> 1;
        if (edge_dst[mid] < d) lo = mid + 1; else hi = mid;
    }
    g_nstart[d] = lo;
}

// pack wk_w / wv_w into bf16 hi/lo padded tiles (exact smem layout)
__global__ void wconv_kernel(const float* __restrict__ wk_w,
                             const float* __restrict__ wv_w) {
    int idx = blockIdx.x * blockDim.x + threadIdx.x;   // over 2*128*KPAD
    if (idx >= 2 * DIMF * KPAD) return;
    int mat = idx / (DIMF * KPAD);
    int rem = idx - mat * (DIMF * KPAD);
    int n   = rem / KPAD;
    int k   = rem - n * KPAD;
    float v = (k < LDKV) ? (mat == 0 ? wk_w : wv_w)[(size_t)n * LDKV + k] : 0.f;
    __nv_bfloat16 h = __float2bfloat16(v);
    __nv_bfloat16 l = __float2bfloat16(v - __bfloat162float(h));
    int chunk = k >> 7, kc = k & 127;
    int n2 = mat * DIMF + n;                            // 0..255 concat row
    unsigned short* ph = (unsigned short*)&g_W2[0][chunk][0];
    unsigned short* pl = (unsigned short*)&g_W2[1][chunk][0];
    ph[n2 * (ROWU32 * 2) + kc] = __bfloat16_as_ushort(h);
    pl[n2 * (ROWU32 * 2) + kc] = __bfloat16_as_ushort(l);
}

// ---------------- bf16 mma.sync helper ----------------
__device__ __forceinline__ void mma16816(float* c, const uint32_t* a, const uint32_t* b) {
    asm volatile(
        "mma.sync.aligned.m16n8k16.row.col.f32.bf16.bf16.f32 "
        "{%0,%1,%2,%3}, {%4,%5,%6,%7}, {%8,%9}, {%0,%1,%2,%3};"
        : "+f"(c[0]), "+f"(c[1]), "+f"(c[2]), "+f"(c[3])
        : "r"(a[0]), "r"(a[1]), "r"(a[2]), "r"(a[3]), "r"(b[0]), "r"(b[1]));
}

// ---------------- fused K+V projection via mma.sync (bf16 hi/lo 3-pass) ----------------
// smem: Ah[128*68] Al[128*68] Wh[256*68] Wl[256*68] u32  => 208,896 B
#define KV_SMEM ((2 * 128 * ROWU32 + 2 * 256 * ROWU32) * 4)

__global__ __launch_bounds__(256, 1)
void gemm_kv_mma(const float* __restrict__ sf, const int* __restrict__ sidx,
                 const float* __restrict__ ef, const float* __restrict__ edt,
                 const float* __restrict__ tw, const float* __restrict__ tb,
                 const float* __restrict__ wk_b, const float* __restrict__ wv_b,
                 int D, int E) {
    extern __shared__ uint32_t sm[];
    uint32_t* Ah = sm;
    uint32_t* Al = Ah + 128 * ROWU32;
    uint32_t* Wh = Al + 128 * ROWU32;
    uint32_t* Wl = Wh + 256 * ROWU32;

    const int tid  = threadIdx.x;
    const int wid  = tid >> 5;
    const int lane = tid & 31;
    const int g    = lane >> 2;       // group 0..7
    const int t    = lane & 3;        // thread-in-group
    const int mb   = (wid >> 2) * 64; // warp M base (0 or 64)
    const int nb   = (wid & 3) * 64;  // warp N base (0..192)
    const int tile0 = blockIdx.x * 128;

    float acc[4][8][4];
    #pragma unroll
    for (int i = 0; i < 4; i++)
        #pragma unroll
        for (int j = 0; j < 8; j++)
            #pragma unroll
            for (int q = 0; q < 4; q++) acc[i][j][q] = 0.f;

    for (int c = 0; c < NCHUNK; c++) {
        __syncthreads();   // previous iteration's frag reads done

        // ---- copy packed weight chunk (layout-identical) ----
        {
            uint4* dh = (uint4*)Wh;
            uint4* dl = (uint4*)Wl;
            const uint4* shp = g_W2[0][c];
            const uint4* slp = g_W2[1][c];
            #pragma unroll 4
            for (int i = tid; i < 256 * (ROWU32 / 4); i += 256) {
                dh[i] = shp[i]; dl[i] = slp[i];
            }
        }
        // ---- build A tile (gather + time features), hi/lo split ----
        for (int gi = tid; gi < 2048; gi += 256) {
            int r  = gi >> 4;
            int kc = (gi & 15) * 8;
            int gr = tile0 + r;
            int kg = c * 128 + kc;
            float v[8];
            #pragma unroll
            for (int j = 0; j < 8; j++) v[j] = 0.f;
            if (gr < E) {
                if (kg < DIMF) {
                    const float* p = sf + (size_t)sidx[D + gr] * DIMF + kg;
                    float4 a = *(const float4*)p;
                    float4 b = *(const float4*)(p + 4);
                    v[0]=a.x; v[1]=a.y; v[2]=a.z; v[3]=a.w;
                    v[4]=b.x; v[5]=b.y; v[6]=b.z; v[7]=b.w;
                } else if (kg < 2 * DIMF) {
                    const float* p = ef + (size_t)gr * DIMF + (kg - DIMF);
                    float4 a = *(const float4*)p;
                    float4 b = *(const float4*)(p + 4);
                    v[0]=a.x; v[1]=a.y; v[2]=a.z; v[3]=a.w;
                    v[4]=b.x; v[5]=b.y; v[6]=b.z; v[7]=b.w;
                } else {
                    float dt = edt[gr];
                    #pragma unroll
                    for (int j = 0; j < 8; j++) {
                        int kk = kg + j;
                        if (kk < LDKV) {
                            int tt = kk - 2 * DIMF;
                            v[j] = cosf(dt * tw[tt] + tb[tt]);
                        }
                    }
                }
            }
            uint32_t hp[4], lp[4];
            #pragma unroll
            for (int j = 0; j < 4; j++) {
                __nv_bfloat16 h0 = __float2bfloat16(v[2*j]);
                __nv_bfloat16 h1 = __float2bfloat16(v[2*j+1]);
                __nv_bfloat16 l0 = __float2bfloat16(v[2*j]   - __bfloat162float(h0));
                __nv_bfloat16 l1 = __float2bfloat16(v[2*j+1] - __bfloat162float(h1));
                hp[j] = (uint32_t)__bfloat16_as_ushort(h0) | ((uint32_t)__bfloat16_as_ushort(h1) << 16);
                lp[j] = (uint32_t)__bfloat16_as_ushort(l0) | ((uint32_t)__bfloat16_as_ushort(l1) << 16);
            }
            int w0 = r * ROWU32 + (kc >> 1);
            *(uint4*)&Ah[w0] = make_uint4(hp[0], hp[1], hp[2], hp[3]);
            *(uint4*)&Al[w0] = make_uint4(lp[0], lp[1], lp[2], lp[3]);
        }
        __syncthreads();

        // ---- 3 passes: Ah*Wh + Al*Wh + Ah*Wl ----
        #pragma unroll
        for (int p = 0; p < 3; p++) {
            const uint32_t* Ap = (p == 1) ? Al : Ah;
            const uint32_t* Wp = (p == 2) ? Wl : Wh;
            #pragma unroll
            for (int ks = 0; ks < 8; ks++) {
                const int k2 = ks * 8;
                uint32_t af[4][4];
                #pragma unroll
                for (int mt = 0; mt < 4; mt++) {
                    const uint32_t* base = Ap + (mb + mt * 16 + g) * ROWU32 + k2 + t;
                    af[mt][0] = base[0];
                    af[mt][1] = base[8 * ROWU32];
                    af[mt][2] = base[4];
                    af[mt][3] = base[8 * ROWU32 + 4];
                }
                uint32_t bf[8][2];
                #pragma unroll
                for (int nt = 0; nt < 8; nt++) {
                    const uint32_t* base = Wp + (nb + nt * 8 + g) * ROWU32 + k2 + t;
                    bf[nt][0] = base[0];
                    bf[nt][1] = base[4];
                }
                #pragma unroll
                for (int mt = 0; mt < 4; mt++)
                    #pragma unroll
                    for (int nt = 0; nt < 8; nt++)
                        mma16816(acc[mt][nt], af[mt], bf[nt]);
            }
        }
    }

    // ---- epilogue: bias + scatter to g_K / g_V ----
    #pragma unroll
    for (int nt = 0; nt < 8; nt++) {
        int col = nb + nt * 8 + 2 * t;          // even, pair (col, col+1) same matrix
        bool isK = (col < DIMF);
        int cc = isK ? col : col - DIMF;
        float b0 = isK ? __ldg(&wk_b[cc]) : __ldg(&wv_b[cc]);
        float b1 = isK ? __ldg(&wk_b[cc + 1]) : __ldg(&wv_b[cc + 1]);
        float* out = isK ? g_K : g_V;
        #pragma unroll
        for (int mt = 0; mt < 4; mt++) {
            int r0 = tile0 + mb + mt * 16 + g;
            int r1 = r0 + 8;
            if (r0 < E) {
                float2 v = make_float2(acc[mt][nt][0] + b0, acc[mt][nt][1] + b1);
                *(float2*)&out[(size_t)r0 * DIMF + cc] = v;
            }
            if (r1 < E) {
                float2 v = make_float2(acc[mt][nt][2] + b0, acc[mt][nt][3] + b1);
                *(float2*)&out[(size_t)r1 * DIMF + cc] = v;
            }
        }
    }
}

// ---------------- scalar SGEMM for Q and out projections ----------------
template<int MODE>
__device__ __forceinline__ float fetchA(int row, int k,
                                        const float* __restrict__ sf,
                                        const int* __restrict__ sidx) {
    if (MODE == 0) {
        return sf[(size_t)sidx[row] * DIMF + k];
    } else {
        if (k < DIMF) return g_h[(size_t)row * DIMF + k];
        else          return sf[(size_t)sidx[row] * DIMF + (k - DIMF)];
    }
}

template<int MODE>
__global__ __launch_bounds__(256)
void gemm_tn(const float* __restrict__ W, int ldw, int ktot,
             const float* __restrict__ bias, int outsel, int M,
             const float* __restrict__ sf, const int* __restrict__ sidx) {
    __shared__ float As[16][132];
    __shared__ float Bs[16][132];

    float* out = (outsel == 0) ? g_Q : g_rst;

    const int tid = threadIdx.x;
    const int i0  = blockIdx.x * 128;
    const int lr  = tid >> 1;
    const int lk  = (tid & 1) * 8;
    const int tx  = tid & 15;
    const int ty  = tid >> 4;

    float acc[8][8];
    #pragma unroll
    for (int i = 0; i < 8; i++)
        #pragma unroll
        for (int j = 0; j < 8; j++) acc[i][j] = 0.f;

    for (int k0 = 0; k0 < ktot; k0 += 16) {
        {
            int row = i0 + lr;
            #pragma unroll
            for (int j = 0; j < 8; j++) {
                int k = k0 + lk + j;
                float v = 0.f;
                if (row < M && k < ktot) v = fetchA<MODE>(row, k, sf, sidx);
                As[lk + j][lr] = v;
            }
        }
        {
            #pragma unroll
            for (int j = 0; j < 8; j++) {
                int k = k0 + lk + j;
                Bs[lk + j][lr] = (k < ktot) ? W[(size_t)lr * ldw + k] : 0.f;
            }
        }
        __syncthreads();

        #pragma unroll
        for (int kk = 0; kk < 16; kk++) {
            float4 a0 = *(const float4*)&As[kk][ty * 8];
            float4 a1 = *(const float4*)&As[kk][ty * 8 + 4];
            float4 b0 = *(const float4*)&Bs[kk][tx * 8];
            float4 b1 = *(const float4*)&Bs[kk][tx * 8 + 4];
            float ar[8] = {a0.x, a0.y, a0.z, a0.w, a1.x, a1.y, a1.z, a1.w};
            float br[8] = {b0.x, b0.y, b0.z, b0.w, b1.x, b1.y, b1.z, b1.w};
            #pragma unroll
            for (int i = 0; i < 8; i++)
                #pragma unroll
                for (int j = 0; j < 8; j++)
                    acc[i][j] += ar[i] * br[j];
        }
        __syncthreads();
    }

    #pragma unroll
    for (int i = 0; i < 8; i++) {
        int row = i0 + ty * 8 + i;
        if (row >= M) continue;
        #pragma unroll
        for (int j = 0; j < 8; j++) {
            int col = tx * 8 + j;
            float b = (MODE == 0) ? g_qb2[col] : bias[col];
            float v = acc[i][j] + b;
            if (MODE == 2) v = fmaxf(v, 0.f);
            out[(size_t)row * DIMF + col] = v;
        }
    }
}

// ---------------- per-destination online-softmax attention ----------------
__global__ __launch_bounds__(256)
void attn_kernel(int D) {
    int w = (blockIdx.x * blockDim.x + threadIdx.x) >> 5;
    int lane = threadIdx.x & 31;
    if (w >= D) return;

    int s = g_nstart[w];
    int e = g_nstart[w + 1];

    float4 q = *(const float4*)&g_Q[(size_t)w * DIMF + lane * 4];

    float m = -3.402823466e38f;
    float den = 0.f;
    float4 acc = make_float4(0.f, 0.f, 0.f, 0.f);

    for (int i = s; i < e; i++) {
        float4 k4 = *(const float4*)&g_K[(size_t)i * DIMF + lane * 4];
        float dot = q.x * k4.x + q.y * k4.y + q.z * k4.z + q.w * k4.w;
        dot += __shfl_xor_sync(0xffffffffu, dot, 1);
        dot += __shfl_xor_sync(0xffffffffu, dot, 2);
        float sc = (dot > 0.f) ? dot : 0.2f * dot;
        float nm = fmaxf(m, sc);
        float c  = expf(m - nm);
        float wt = expf(sc - nm);
        float4 v4 = *(const float4*)&g_V[(size_t)i * DIMF + lane * 4];
        acc.x = acc.x * c + wt * v4.x;
        acc.y = acc.y * c + wt * v4.y;
        acc.z = acc.z * c + wt * v4.z;
        acc.w = acc.w * c + wt * v4.w;
        den = den * c + wt;
        m = nm;
    }

    float inv = (e > s) ? 1.f / den : 0.f;
    float4 o = make_float4(acc.x * inv, acc.y * inv, acc.z * inv, acc.w * inv);
    *(float4*)&g_h[(size_t)w * DIMF + lane * 4] = o;
}

// ---------------- layernorm ----------------
__global__ __launch_bounds__(256)
void ln_kernel(const float* __restrict__ ln_g, const float* __restrict__ ln_b,
               float* __restrict__ out, int D) {
    int row = (blockIdx.x * blockDim.x + threadIdx.x) >> 5;
    int lane = threadIdx.x & 31;
    if (row >= D) return;

    float4 v = *(const float4*)&g_rst[(size_t)row * DIMF + lane * 4];
    float s  = v.x + v.y + v.z + v.w;
    float s2 = v.x * v.x + v.y * v.y + v.z * v.z + v.w * v.w;
    #pragma unroll
    for (int off = 16; off > 0; off >>= 1) {
        s  += __shfl_xor_sync(0xffffffffu, s,  off);
        s2 += __shfl_xor_sync(0xffffffffu, s2, off);
    }
    float mean = s * (1.f / DIMF);
    float var  = s2 * (1.f / DIMF) - mean * mean;
    float rstd = rsqrtf(var + LN_EPS);

    float4 g = *(const float4*)&ln_g[lane * 4];
    float4 b = *(const float4*)&ln_b[lane * 4];
    float4 o;
    o.x = (v.x - mean) * rstd * g.x + b.x;
    o.y = (v.y - mean) * rstd * g.y + b.y;
    o.z = (v.z - mean) * rstd * g.z + b.z;
    o.w = (v.w - mean) * rstd * g.w + b.w;
    *(float4*)&out[(size_t)row * DIMF + lane * 4] = o;
}

// ---------------- launcher ----------------
extern "C" void kernel_launch(void* const* d_in, const int* in_sizes, int n_in,
                              void* d_out, int out_size) {
    const float* src_feat = (const float*)d_in[0];
    const float* edge_f   = (const float*)d_in[1];
    const float* edge_dt  = (const float*)d_in[2];
    const float* time_w   = (const float*)d_in[3];
    const float* time_b   = (const float*)d_in[4];
    const float* wq_w     = (const float*)d_in[5];
    const float* wq_b     = (const float*)d_in[6];
    const float* wk_w     = (const float*)d_in[7];
    const float* wk_b     = (const float*)d_in[8];
    const float* wv_w     = (const float*)d_in[9];
    const float* wv_b     = (const float*)d_in[10];
    const float* wout_w   = (const float*)d_in[11];
    const float* wout_b   = (const float*)d_in[12];
    const float* ln_g     = (const float*)d_in[13];
    const float* ln_b     = (const float*)d_in[14];
    const int*   src_idx  = (const int*)d_in[15];
    const int*   edge_dst = (const int*)d_in[16];

    const int E = in_sizes[1] / DIMF;
    const int D = in_sizes[0] / DIMF - E;

    static bool attr_set = []() {
        cudaFuncSetAttribute(gemm_kv_mma,
                             cudaFuncAttributeMaxDynamicSharedMemorySize, KV_SMEM);
        return true;
    }();
    (void)attr_set;

    qb2_kernel<<<1, 128>>>(wq_w, wq_b, time_b);
    nstart_kernel<<<(D + 1 + 255) / 256, 256>>>(edge_dst, E, D);
    wconv_kernel<<<(2 * DIMF * KPAD + 255) / 256, 256>>>(wk_w, wv_w);

    // Q projection (scalar; small)
    gemm_tn<0><<<(D + 127) / 128, 256>>>(wq_w, LDQ, DIMF, wq_b, 0, D,
                                         src_feat, src_idx);

    // fused K+V projection on HMMA tensor cores (bf16 hi/lo, fp32 accumulate)
    gemm_kv_mma<<<(E + 127) / 128, 256, KV_SMEM>>>(src_feat, src_idx, edge_f,
                                                   edge_dt, time_w, time_b,
                                                   wk_b, wv_b, D, E);

    attn_kernel<<<(D + 7) / 8, 256>>>(D);

    gemm_tn<2><<<(D + 127) / 128, 256>>>(wout_w, LDOUT, LDOUT, wout_b, 3, D,
                                         src_feat, src_idx);

    ln_kernel<<<(D + 7) / 8, 256>>>(ln_g, ln_b, (float*)d_out, D);
}

// round 8
// speedup vs baseline: 1.5379x; 1.1518x over previous
#include <cuda_runtime.h>
#include <cuda_bf16.h>
#include <math.h>
#include <stdint.h>

// ---------------- problem constants ----------------
#define DIMF     128
#define DTIME    100
#define LDQ      228
#define LDKV     356
#define LDOUT    256
#define MAXD     25024
#define MAXE     250048
#define LN_EPS   1e-5f
#define KX       384      // padded kv-input dim (356 + bias col at 356, zeros after)
#define NEG_INF  (-3.402823466e38f)

// ---------------- device scratch (static, allocation-free) ----------------
__device__ float g_Q   [(size_t)MAXD * DIMF];
__device__ float g_h   [(size_t)MAXD * DIMF];
__device__ float g_rst [(size_t)MAXD * DIMF];
__device__ float g_qb2 [DIMF];
__device__ int   g_nstart[MAXD + 2];
__device__ float g_tQ  [(size_t)MAXD * 8 * KX];   // per-dst folded query: tQ[d][h][k]
__device__ float g_xbar[(size_t)MAXD * 8 * KX];   // per-dst att-weighted input sums
__device__ float g_S   [(size_t)MAXE * 8];        // leaky scores per edge/head

// ---------------- small precompute kernels ----------------
__global__ void qb2_kernel(const float* __restrict__ wq_w,
                           const float* __restrict__ wq_b,
                           const float* __restrict__ time_b) {
    int o = threadIdx.x;
    if (o >= DIMF) return;
    float s = wq_b[o];
    #pragma unroll 4
    for (int t = 0; t < DTIME; t++)
        s += wq_w[(size_t)o * LDQ + DIMF + t] * cosf(time_b[t]);
    g_qb2[o] = s;
}

__global__ void nstart_kernel(const int* __restrict__ edge_dst, int E, int D) {
    int d = blockIdx.x * blockDim.x + threadIdx.x;
    if (d > D) return;
    int lo = 0, hi = E;
    while (lo < hi) {
        int mid = (lo + hi) >> 1;
        if (edge_dst[mid] < d) lo = mid + 1; else hi = mid;
    }
    g_nstart[d] = lo;
}

// ---------------- Q projection (scalar SGEMM, small) ----------------
__global__ __launch_bounds__(256)
void gemm_q(const float* __restrict__ W,
            const float* __restrict__ sf, const int* __restrict__ sidx, int M) {
    __shared__ float As[16][132];
    __shared__ float Bs[16][132];

    const int tid = threadIdx.x;
    const int i0  = blockIdx.x * 128;
    const int lr  = tid >> 1;
    const int lk  = (tid & 1) * 8;
    const int tx  = tid & 15;
    const int ty  = tid >> 4;

    float acc[8][8];
    #pragma unroll
    for (int i = 0; i < 8; i++)
        #pragma unroll
        for (int j = 0; j < 8; j++) acc[i][j] = 0.f;

    for (int k0 = 0; k0 < DIMF; k0 += 16) {
        {
            int row = i0 + lr;
            #pragma unroll
            for (int j = 0; j < 8; j++) {
                int k = k0 + lk + j;
                As[lk + j][lr] = (row < M) ? sf[(size_t)sidx[row] * DIMF + k] : 0.f;
            }
        }
        {
            #pragma unroll
            for (int j = 0; j < 8; j++) {
                int k = k0 + lk + j;
                Bs[lk + j][lr] = W[(size_t)lr * LDQ + k];
            }
        }
        __syncthreads();
        #pragma unroll
        for (int kk = 0; kk < 16; kk++) {
            float4 a0 = *(const float4*)&As[kk][ty * 8];
            float4 a1 = *(const float4*)&As[kk][ty * 8 + 4];
            float4 b0 = *(const float4*)&Bs[kk][tx * 8];
            float4 b1 = *(const float4*)&Bs[kk][tx * 8 + 4];
            float ar[8] = {a0.x, a0.y, a0.z, a0.w, a1.x, a1.y, a1.z, a1.w};
            float br[8] = {b0.x, b0.y, b0.z, b0.w, b1.x, b1.y, b1.z, b1.w};
            #pragma unroll
            for (int i = 0; i < 8; i++)
                #pragma unroll
                for (int j = 0; j < 8; j++)
                    acc[i][j] += ar[i] * br[j];
        }
        __syncthreads();
    }
    #pragma unroll
    for (int i = 0; i < 8; i++) {
        int row = i0 + ty * 8 + i;
        if (row >= M) continue;
        #pragma unroll
        for (int j = 0; j < 8; j++) {
            int col = tx * 8 + j;
            g_Q[(size_t)row * DIMF + col] = acc[i][j] + g_qb2[col];
        }
    }
}

// ---------------- tQ: fold Wk into per-destination queries ----------------
// tQ[d][h][k] = sum_j Q[d, 16h+j] * wk_ext[16h+j, k]
// wk_ext[:,356] = wk_b (homogeneous bias col), wk_ext[:,357..383] = 0
__global__ __launch_bounds__(256)
void tq_kernel(const float* __restrict__ wk, const float* __restrict__ wk_b, int D) {
    int gw   = (blockIdx.x * 256 + threadIdx.x) >> 5;
    int lane = threadIdx.x & 31;
    int d0   = gw * 4;
    if (d0 >= D) return;

    for (int h = 0; h < 8; h++) {
        float Qr[4][16];
        #pragma unroll
        for (int dd = 0; dd < 4; dd++) {
            int d = d0 + dd;
            #pragma unroll
            for (int j = 0; j < 16; j++)
                Qr[dd][j] = (d < D) ? g_Q[(size_t)d * DIMF + h * 16 + j] : 0.f;
        }
        #pragma unroll
        for (int t = 0; t < 12; t++) {
            int k = lane + 32 * t;
            float wkr[16];
            #pragma unroll
            for (int j = 0; j < 16; j++) {
                int rc = h * 16 + j;
                wkr[j] = (k < LDKV) ? wk[(size_t)rc * LDKV + k]
                                    : (k == LDKV ? wk_b[rc] : 0.f);
            }
            #pragma unroll
            for (int dd = 0; dd < 4; dd++) {
                float s = 0.f;
                #pragma unroll
                for (int j = 0; j < 16; j++) s = fmaf(Qr[dd][j], wkr[j], s);
                int d = d0 + dd;
                if (d < D) g_tQ[((size_t)d * 8 + h) * KX + k] = s;
            }
        }
    }
}

// ---------------- edge kernel: scores + softmax + xbar (warp per dst) ----------------
__device__ __forceinline__ void load_x(float* xv, int lane, int e,
                                       const float* __restrict__ sf,
                                       const int* __restrict__ sidx,
                                       const float* __restrict__ ef,
                                       const float* __restrict__ edt,
                                       const float* __restrict__ tw,
                                       const float* __restrict__ tb,
                                       int D) {
    int row = sidx[D + e];
    float dt = edt[e];
    #pragma unroll
    for (int t = 0; t < 4; t++)
        xv[t] = sf[(size_t)row * DIMF + lane + 32 * t];
    #pragma unroll
    for (int t = 4; t < 8; t++)
        xv[t] = ef[(size_t)e * DIMF + lane + 32 * t - DIMF];
    #pragma unroll
    for (int t = 8; t < 11; t++) {
        int ti = lane + 32 * t - 2 * DIMF;
        xv[t] = __cosf(fmaf(dt, tw[ti], tb[ti]));
    }
    {
        int k = lane + 32 * 11;
        if (k < LDKV)       xv[11] = __cosf(fmaf(dt, tw[k - 2 * DIMF], tb[k - 2 * DIMF]));
        else if (k == LDKV) xv[11] = 1.f;     // homogeneous coord
        else                xv[11] = 0.f;
    }
}

__global__ __launch_bounds__(128)
void edge_kernel(const float* __restrict__ sf, const int* __restrict__ sidx,
                 const float* __restrict__ ef, const float* __restrict__ edt,
                 const float* __restrict__ tw, const float* __restrict__ tb,
                 int D, int E) {
    int d    = (blockIdx.x * 128 + threadIdx.x) >> 5;
    int lane = threadIdx.x & 31;
    if (d >= D) return;

    int s0 = g_nstart[d];
    int e0 = g_nstart[d + 1];

    float m[8], den[8];
    #pragma unroll
    for (int h = 0; h < 8; h++) { m[h] = NEG_INF; den[h] = 0.f; }

    // ---- pass 1: scores + online max/den ----
    {
        float tQr[8][12];
        #pragma unroll
        for (int h = 0; h < 8; h++)
            #pragma unroll
            for (int t = 0; t < 12; t++)
                tQr[h][t] = g_tQ[((size_t)d * 8 + h) * KX + lane + 32 * t];

        for (int e = s0; e < e0; e++) {
            float xv[12];
            load_x(xv, lane, e, sf, sidx, ef, edt, tw, tb, D);
            float sh[8];
            #pragma unroll
            for (int h = 0; h < 8; h++) sh[h] = 0.f;
            #pragma unroll
            for (int t = 0; t < 12; t++)
                #pragma unroll
                for (int h = 0; h < 8; h++)
                    sh[h] = fmaf(tQr[h][t], xv[t], sh[h]);
            #pragma unroll
            for (int h = 0; h < 8; h++) {
                #pragma unroll
                for (int o = 16; o > 0; o >>= 1)
                    sh[h] += __shfl_xor_sync(0xffffffffu, sh[h], o);
                sh[h] = (sh[h] > 0.f) ? sh[h] : 0.2f * sh[h];   // leaky_relu 0.2
            }
            if (lane < 8) g_S[(size_t)e * 8 + lane] = sh[lane];
            #pragma unroll
            for (int h = 0; h < 8; h++) {
                float nm = fmaxf(m[h], sh[h]);
                den[h] = den[h] * __expf(m[h] - nm) + __expf(sh[h] - nm);
                m[h] = nm;
            }
        }
    }

    float inv[8];
    #pragma unroll
    for (int h = 0; h < 8; h++) inv[h] = (den[h] > 0.f) ? 1.f / den[h] : 0.f;

    // ---- pass 2: att-weighted accumulation of x into xbar ----
    float xacc[8][12];
    #pragma unroll
    for (int h = 0; h < 8; h++)
        #pragma unroll
        for (int t = 0; t < 12; t++) xacc[h][t] = 0.f;

    for (int e = s0; e < e0; e++) {
        float att[8];
        #pragma unroll
        for (int h = 0; h < 8; h++)
            att[h] = __expf(g_S[(size_t)e * 8 + h] - m[h]) * inv[h];
        float xv[12];
        load_x(xv, lane, e, sf, sidx, ef, edt, tw, tb, D);
        #pragma unroll
        for (int h = 0; h < 8; h++)
            #pragma unroll
            for (int t = 0; t < 12; t++)
                xacc[h][t] = fmaf(att[h], xv[t], xacc[h][t]);
    }

    #pragma unroll
    for (int h = 0; h < 8; h++)
        #pragma unroll
        for (int t = 0; t < 12; t++)
            g_xbar[((size_t)d * 8 + h) * KX + lane + 32 * t] = xacc[h][t];
}

// ---------------- hproj: h[d] = Wv_ext @ xbar[d] (warp per dst) ----------------
// wv_ext[:,356] = wv_b; xbar[·][356] = sum(att) so bias & empty segments are exact.
__global__ __launch_bounds__(128)
void hproj_kernel(const float* __restrict__ wv, const float* __restrict__ wv_b, int D) {
    int d    = (blockIdx.x * 128 + threadIdx.x) >> 5;
    int lane = threadIdx.x & 31;
    if (d >= D) return;

    for (int hh = 0; hh < 8; hh++) {
        float xr[12];
        #pragma unroll
        for (int t = 0; t < 12; t++)
            xr[t] = g_xbar[((size_t)d * 8 + hh) * KX + lane + 32 * t];
        #pragma unroll
        for (int j = 0; j < 16; j++) {
            int c = hh * 16 + j;
            float p = 0.f;
            #pragma unroll
            for (int t = 0; t < 12; t++) {
                int k = lane + 32 * t;
                float w = (k < LDKV) ? wv[(size_t)c * LDKV + k]
                                     : (k == LDKV ? wv_b[c] : 0.f);
                p = fmaf(w, xr[t], p);
            }
            #pragma unroll
            for (int o = 16; o > 0; o >>= 1)
                p += __shfl_xor_sync(0xffffffffu, p, o);
            if (lane == 0) g_h[(size_t)d * DIMF + c] = p;
        }
    }
}

// ---------------- output projection + ReLU (scalar SGEMM) ----------------
__global__ __launch_bounds__(256)
void gemm_out(const float* __restrict__ W, const float* __restrict__ bias,
              const float* __restrict__ sf, const int* __restrict__ sidx, int M) {
    __shared__ float As[16][132];
    __shared__ float Bs[16][132];

    const int tid = threadIdx.x;
    const int i0  = blockIdx.x * 128;
    const int lr  = tid >> 1;
    const int lk  = (tid & 1) * 8;
    const int tx  = tid & 15;
    const int ty  = tid >> 4;

    float acc[8][8];
    #pragma unroll
    for (int i = 0; i < 8; i++)
        #pragma unroll
        for (int j = 0; j < 8; j++) acc[i][j] = 0.f;

    for (int k0 = 0; k0 < LDOUT; k0 += 16) {
        {
            int row = i0 + lr;
            #pragma unroll
            for (int j = 0; j < 8; j++) {
                int k = k0 + lk + j;
                float v = 0.f;
                if (row < M) {
                    if (k < DIMF) v = g_h[(size_t)row * DIMF + k];
                    else          v = sf[(size_t)sidx[row] * DIMF + (k - DIMF)];
                }
                As[lk + j][lr] = v;
            }
        }
        {
            #pragma unroll
            for (int j = 0; j < 8; j++) {
                int k = k0 + lk + j;
                Bs[lk + j][lr] = W[(size_t)lr * LDOUT + k];
            }
        }
        __syncthreads();
        #pragma unroll
        for (int kk = 0; kk < 16; kk++) {
            float4 a0 = *(const float4*)&As[kk][ty * 8];
            float4 a1 = *(const float4*)&As[kk][ty * 8 + 4];
            float4 b0 = *(const float4*)&Bs[kk][tx * 8];
            float4 b1 = *(const float4*)&Bs[kk][tx * 8 + 4];
            float ar[8] = {a0.x, a0.y, a0.z, a0.w, a1.x, a1.y, a1.z, a1.w};
            float br[8] = {b0.x, b0.y, b0.z, b0.w, b1.x, b1.y, b1.z, b1.w};
            #pragma unroll
            for (int i = 0; i < 8; i++)
                #pragma unroll
                for (int j = 0; j < 8; j++)
                    acc[i][j] += ar[i] * br[j];
        }
        __syncthreads();
    }
    #pragma unroll
    for (int i = 0; i < 8; i++) {
        int row = i0 + ty * 8 + i;
        if (row >= M) continue;
        #pragma unroll
        for (int j = 0; j < 8; j++) {
            int col = tx * 8 + j;
            g_rst[(size_t)row * DIMF + col] = fmaxf(acc[i][j] + bias[col], 0.f);
        }
    }
}

// ---------------- layernorm (warp per row) ----------------
__global__ __launch_bounds__(256)
void ln_kernel(const float* __restrict__ ln_g, const float* __restrict__ ln_b,
               float* __restrict__ out, int D) {
    int row = (blockIdx.x * blockDim.x + threadIdx.x) >> 5;
    int lane = threadIdx.x & 31;
    if (row >= D) return;

    float4 v = *(const float4*)&g_rst[(size_t)row * DIMF + lane * 4];
    float s  = v.x + v.y + v.z + v.w;
    float s2 = v.x * v.x + v.y * v.y + v.z * v.z + v.w * v.w;
    #pragma unroll
    for (int off = 16; off > 0; off >>= 1) {
        s  += __shfl_xor_sync(0xffffffffu, s,  off);
        s2 += __shfl_xor_sync(0xffffffffu, s2, off);
    }
    float mean = s * (1.f / DIMF);
    float var  = s2 * (1.f / DIMF) - mean * mean;
    float rstd = rsqrtf(var + LN_EPS);

    float4 g = *(const float4*)&ln_g[lane * 4];
    float4 b = *(const float4*)&ln_b[lane * 4];
    float4 o;
    o.x = (v.x - mean) * rstd * g.x + b.x;
    o.y = (v.y - mean) * rstd * g.y + b.y;
    o.z = (v.z - mean) * rstd * g.z + b.z;
    o.w = (v.w - mean) * rstd * g.w + b.w;
    *(float4*)&out[(size_t)row * DIMF + lane * 4] = o;
}

// ---------------- launcher ----------------
extern "C" void kernel_launch(void* const* d_in, const int* in_sizes, int n_in,
                              void* d_out, int out_size) {
    const float* src_feat = (const float*)d_in[0];
    const float* edge_f   = (const float*)d_in[1];
    const float* edge_dt  = (const float*)d_in[2];
    const float* time_w   = (const float*)d_in[3];
    const float* time_b   = (const float*)d_in[4];
    const float* wq_w     = (const float*)d_in[5];
    const float* wq_b     = (const float*)d_in[6];
    const float* wk_w     = (const float*)d_in[7];
    const float* wk_b     = (const float*)d_in[8];
    const float* wv_w     = (const float*)d_in[9];
    const float* wv_b     = (const float*)d_in[10];
    const float* wout_w   = (const float*)d_in[11];
    const float* wout_b   = (const float*)d_in[12];
    const float* ln_g     = (const float*)d_in[13];
    const float* ln_b     = (const float*)d_in[14];
    const int*   src_idx  = (const int*)d_in[15];   // JAX x64-disabled: int32
    const int*   edge_dst = (const int*)d_in[16];   // JAX x64-disabled: int32

    const int E = in_sizes[1] / DIMF;
    const int D = in_sizes[0] / DIMF - E;

    qb2_kernel<<<1, 128>>>(wq_w, wq_b, time_b);
    nstart_kernel<<<(D + 1 + 255) / 256, 256>>>(edge_dst, E, D);

    // Qd = gathered node feats @ wq[:, :128]^T + qb2
    gemm_q<<<(D + 127) / 128, 256>>>(wq_w, src_feat, src_idx, D);

    // tQ[d,h,:] = Wk_h^T Q_h[d]  (folds K projection into destinations)
    {
        int warps = (D + 3) / 4;
        tq_kernel<<<(warps * 32 + 255) / 256, 256>>>(wk_w, wk_b, D);
    }

    // per-destination scores + softmax + att-weighted x accumulation
    edge_kernel<<<(D + 3) / 4, 128>>>(src_feat, src_idx, edge_f, edge_dt,
                                      time_w, time_b, D, E);

    // h[d] = Wv @ xbar[d] (+ bias via homogeneous coordinate)
    hproj_kernel<<<(D + 3) / 4, 128>>>(wv_w, wv_b, D);

    // output projection + ReLU
    gemm_out<<<(D + 127) / 128, 256>>>(wout_w, wout_b, src_feat, src_idx, D);

    ln_kernel<<<(D + 7) / 8, 256>>>(ln_g, ln_b, (float*)d_out, D);
}

// round 10
// speedup vs baseline: 1.7903x; 1.1641x over previous
#include <cuda_runtime.h>
#include <cuda_bf16.h>
#include <math.h>
#include <stdint.h>

// ---------------- problem constants ----------------
#define DIMF     128
#define DTIME    100
#define LDQ      228
#define LDKV     356
#define LDOUT    256
#define MAXD     25024
#define MAXE     250048
#define LN_EPS   1e-5f
#define KX       384      // padded kv-input dim (356 feats + bias col at 356, zeros after)
#define NEG_INF  (-3.402823466e38f)

// ---------------- device scratch (static, allocation-free) ----------------
__device__ float g_Q   [(size_t)MAXD * DIMF];
__device__ float g_h   [(size_t)MAXD * DIMF];
__device__ float g_rst [(size_t)MAXD * DIMF];
__device__ float g_qb2 [DIMF];
__device__ int   g_nstart[MAXD + 2];
__device__ float g_tQ  [(size_t)MAXD * 8 * KX];   // per-dst folded query: tQ[d][h][k]
__device__ float g_xbar[(size_t)MAXD * 8 * KX];   // per-dst att-weighted input means

// ---------------- small precompute kernels ----------------
__global__ void qb2_kernel(const float* __restrict__ wq_w,
                           const float* __restrict__ wq_b,
                           const float* __restrict__ time_b) {
    int o = threadIdx.x;
    if (o >= DIMF) return;
    float s = wq_b[o];
    #pragma unroll 4
    for (int t = 0; t < DTIME; t++)
        s += wq_w[(size_t)o * LDQ + DIMF + t] * cosf(time_b[t]);
    g_qb2[o] = s;
}

__global__ void nstart_kernel(const int* __restrict__ edge_dst, int E, int D) {
    int d = blockIdx.x * blockDim.x + threadIdx.x;
    if (d > D) return;
    int lo = 0, hi = E;
    while (lo < hi) {
        int mid = (lo + hi) >> 1;
        if (edge_dst[mid] < d) lo = mid + 1; else hi = mid;
    }
    g_nstart[d] = lo;
}

// ---------------- Q projection (scalar SGEMM, small) ----------------
__global__ __launch_bounds__(256)
void gemm_q(const float* __restrict__ W,
            const float* __restrict__ sf, const int* __restrict__ sidx, int M) {
    __shared__ float As[16][132];
    __shared__ float Bs[16][132];

    const int tid = threadIdx.x;
    const int i0  = blockIdx.x * 128;
    const int lr  = tid >> 1;
    const int lk  = (tid & 1) * 8;
    const int tx  = tid & 15;
    const int ty  = tid >> 4;

    float acc[8][8];
    #pragma unroll
    for (int i = 0; i < 8; i++)
        #pragma unroll
        for (int j = 0; j < 8; j++) acc[i][j] = 0.f;

    for (int k0 = 0; k0 < DIMF; k0 += 16) {
        {
            int row = i0 + lr;
            #pragma unroll
            for (int j = 0; j < 8; j++) {
                int k = k0 + lk + j;
                As[lk + j][lr] = (row < M) ? sf[(size_t)sidx[row] * DIMF + k] : 0.f;
            }
        }
        {
            #pragma unroll
            for (int j = 0; j < 8; j++) {
                int k = k0 + lk + j;
                Bs[lk + j][lr] = W[(size_t)lr * LDQ + k];
            }
        }
        __syncthreads();
        #pragma unroll
        for (int kk = 0; kk < 16; kk++) {
            float4 a0 = *(const float4*)&As[kk][ty * 8];
            float4 a1 = *(const float4*)&As[kk][ty * 8 + 4];
            float4 b0 = *(const float4*)&Bs[kk][tx * 8];
            float4 b1 = *(const float4*)&Bs[kk][tx * 8 + 4];
            float ar[8] = {a0.x, a0.y, a0.z, a0.w, a1.x, a1.y, a1.z, a1.w};
            float br[8] = {b0.x, b0.y, b0.z, b0.w, b1.x, b1.y, b1.z, b1.w};
            #pragma unroll
            for (int i = 0; i < 8; i++)
                #pragma unroll
                for (int j = 0; j < 8; j++)
                    acc[i][j] += ar[i] * br[j];
        }
        __syncthreads();
    }
    #pragma unroll
    for (int i = 0; i < 8; i++) {
        int row = i0 + ty * 8 + i;
        if (row >= M) continue;
        #pragma unroll
        for (int j = 0; j < 8; j++) {
            int col = tx * 8 + j;
            g_Q[(size_t)row * DIMF + col] = acc[i][j] + g_qb2[col];
        }
    }
}

// ---------------- tQ: warp per (head, dst-quad), lane = 12 contiguous k ----------------
// tQ[d][h][k] = sum_j Q[d, 16h+j] * wk_ext[16h+j, k];  wk_ext[:,356]=wk_b, rest 0
__global__ __launch_bounds__(256)
void tq_kernel(const float* __restrict__ wk, const float* __restrict__ wk_b, int D) {
    int w    = (blockIdx.x * 256 + threadIdx.x) >> 5;
    int lane = threadIdx.x & 31;
    int nquad = (D + 3) >> 2;
    if (w >= 8 * nquad) return;
    int h  = w & 7;
    int d0 = (w >> 3) * 4;
    int kb = lane * 12;

    // preload Q block: 4 dsts x 16 cols (broadcast loads)
    float Qr[4][16];
    #pragma unroll
    for (int dd = 0; dd < 4; dd++) {
        int d = d0 + dd;
        #pragma unroll
        for (int j = 0; j < 16; j++)
            Qr[dd][j] = (d < D) ? __ldg(&g_Q[(size_t)d * DIMF + h * 16 + j]) : 0.f;
    }

    float acc[4][12];
    #pragma unroll
    for (int dd = 0; dd < 4; dd++)
        #pragma unroll
        for (int i = 0; i < 12; i++) acc[dd][i] = 0.f;

    #pragma unroll
    for (int j = 0; j < 16; j++) {
        int r = h * 16 + j;
        const float* wrow = wk + (size_t)r * LDKV;
        float wr[12];
        #pragma unroll
        for (int i = 0; i < 12; i += 4) {
            int k = kb + i;
            if (k + 3 < LDKV) {
                float4 v = *(const float4*)&wrow[k];
                wr[i] = v.x; wr[i+1] = v.y; wr[i+2] = v.z; wr[i+3] = v.w;
            } else {
                #pragma unroll
                for (int q = 0; q < 4; q++) {
                    int kk = k + q;
                    wr[i+q] = (kk < LDKV) ? wrow[kk] : (kk == LDKV ? __ldg(&wk_b[r]) : 0.f);
                }
            }
        }
        #pragma unroll
        for (int dd = 0; dd < 4; dd++) {
            float q = Qr[dd][j];
            #pragma unroll
            for (int i = 0; i < 12; i++)
                acc[dd][i] = fmaf(q, wr[i], acc[dd][i]);
        }
    }

    #pragma unroll
    for (int dd = 0; dd < 4; dd++) {
        int d = d0 + dd;
        if (d >= D) continue;
        float* out = &g_tQ[((size_t)d * 8 + h) * KX + kb];
        #pragma unroll
        for (int i = 0; i < 12; i += 4)
            *(float4*)&out[i] = make_float4(acc[dd][i], acc[dd][i+1],
                                            acc[dd][i+2], acc[dd][i+3]);
    }
}

// ---------------- edge kernel: ONE pass, online softmax, 4-head groups ----------------
__device__ __forceinline__ void load_x(float* xv, int lane, int e,
                                       const float* __restrict__ sf,
                                       const int* __restrict__ sidx,
                                       const float* __restrict__ ef,
                                       const float* __restrict__ edt,
                                       const float* __restrict__ tw,
                                       const float* __restrict__ tb,
                                       int D) {
    int row = sidx[D + e];
    float dt = edt[e];
    #pragma unroll
    for (int t = 0; t < 4; t++)
        xv[t] = sf[(size_t)row * DIMF + lane + 32 * t];
    #pragma unroll
    for (int t = 4; t < 8; t++)
        xv[t] = ef[(size_t)e * DIMF + lane + 32 * t - DIMF];
    #pragma unroll
    for (int t = 8; t < 11; t++) {
        int ti = lane + 32 * t - 2 * DIMF;
        xv[t] = __cosf(fmaf(dt, tw[ti], tb[ti]));
    }
    {
        int k = lane + 32 * 11;
        if (k < LDKV)       xv[11] = __cosf(fmaf(dt, tw[k - 2 * DIMF], tb[k - 2 * DIMF]));
        else if (k == LDKV) xv[11] = 1.f;     // homogeneous coord (bias / att-mass)
        else                xv[11] = 0.f;
    }
}

__global__ __launch_bounds__(128)
void edge_kernel(const float* __restrict__ sf, const int* __restrict__ sidx,
                 const float* __restrict__ ef, const float* __restrict__ edt,
                 const float* __restrict__ tw, const float* __restrict__ tb,
                 int D, int E) {
    int d    = (blockIdx.x * 128 + threadIdx.x) >> 5;
    int lane = threadIdx.x & 31;
    if (d >= D) return;

    int s0 = g_nstart[d];
    int e0 = g_nstart[d + 1];

    #pragma unroll 1
    for (int hg = 0; hg < 2; hg++) {
        float tQr[4][12];
        #pragma unroll
        for (int hh = 0; hh < 4; hh++)
            #pragma unroll
            for (int t = 0; t < 12; t++)
                tQr[hh][t] = g_tQ[((size_t)d * 8 + hg * 4 + hh) * KX + lane + 32 * t];

        float m[4], den[4], xacc[4][12];
        #pragma unroll
        for (int hh = 0; hh < 4; hh++) {
            m[hh] = NEG_INF; den[hh] = 0.f;
            #pragma unroll
            for (int t = 0; t < 12; t++) xacc[hh][t] = 0.f;
        }

        for (int e = s0; e < e0; e++) {
            float xv[12];
            load_x(xv, lane, e, sf, sidx, ef, edt, tw, tb, D);

            float sh[4];
            #pragma unroll
            for (int hh = 0; hh < 4; hh++) sh[hh] = 0.f;
            #pragma unroll
            for (int t = 0; t < 12; t++)
                #pragma unroll
                for (int hh = 0; hh < 4; hh++)
                    sh[hh] = fmaf(tQr[hh][t], xv[t], sh[hh]);
            #pragma unroll
            for (int hh = 0; hh < 4; hh++) {
                #pragma unroll
                for (int o = 16; o > 0; o >>= 1)
                    sh[hh] += __shfl_xor_sync(0xffffffffu, sh[hh], o);
                sh[hh] = (sh[hh] > 0.f) ? sh[hh] : 0.2f * sh[hh];   // leaky_relu 0.2
            }

            // online softmax-weighted accumulation (warp-uniform branches)
            #pragma unroll
            for (int hh = 0; hh < 4; hh++) {
                if (sh[hh] > m[hh]) {
                    float c = __expf(m[hh] - sh[hh]);   // 0 on first edge
                    den[hh] = fmaf(den[hh], c, 1.f);
                    #pragma unroll
                    for (int t = 0; t < 12; t++)
                        xacc[hh][t] = fmaf(xacc[hh][t], c, xv[t]);
                    m[hh] = sh[hh];
                } else {
                    float wt = __expf(sh[hh] - m[hh]);
                    den[hh] += wt;
                    #pragma unroll
                    for (int t = 0; t < 12; t++)
                        xacc[hh][t] = fmaf(wt, xv[t], xacc[hh][t]);
                }
            }
        }

        #pragma unroll
        for (int hh = 0; hh < 4; hh++) {
            float inv = (den[hh] > 0.f) ? 1.f / den[hh] : 0.f;
            #pragma unroll
            for (int t = 0; t < 12; t++)
                g_xbar[((size_t)d * 8 + hg * 4 + hh) * KX + lane + 32 * t]
                    = xacc[hh][t] * inv;
        }
    }
}

// ---------------- hproj: warp per (head, dst-pair), float4 streaming ----------------
// h[d, 16h+j] = sum_k wv_ext[16h+j, k] * xbar[d][h][k]; bias via homogeneous coord
__global__ __launch_bounds__(256)
void hproj_kernel(const float* __restrict__ wv, const float* __restrict__ wv_b, int D) {
    int w    = (blockIdx.x * 256 + threadIdx.x) >> 5;
    int lane = threadIdx.x & 31;
    int npair = (D + 1) >> 1;
    if (w >= 8 * npair) return;
    int h = w & 7;
    int p = w >> 3;
    int dl = lane >> 4;          // 0..1
    int j  = lane & 15;
    int d  = p * 2 + dl;
    bool valid = (d < D);
    int c = h * 16 + j;

    const float* xrow = g_xbar + ((size_t)(valid ? d : 0) * 8 + h) * KX;
    const float* wrow = wv + (size_t)c * LDKV;

    float acc = 0.f;
    #pragma unroll 4
    for (int k4 = 0; k4 < 89; k4++) {           // k = 0..355
        float4 x = *(const float4*)&xrow[k4 * 4];
        float4 wv4 = *(const float4*)&wrow[k4 * 4];
        acc = fmaf(x.x, wv4.x, acc);
        acc = fmaf(x.y, wv4.y, acc);
        acc = fmaf(x.z, wv4.z, acc);
        acc = fmaf(x.w, wv4.w, acc);
    }
    acc = fmaf(xrow[LDKV], __ldg(&wv_b[c]), acc);   // bias * (att mass)

    if (valid) g_h[(size_t)d * DIMF + c] = acc;
}

// ---------------- output projection + ReLU (scalar SGEMM) ----------------
__global__ __launch_bounds__(256)
void gemm_out(const float* __restrict__ W, const float* __restrict__ bias,
              const float* __restrict__ sf, const int* __restrict__ sidx, int M) {
    __shared__ float As[16][132];
    __shared__ float Bs[16][132];

    const int tid = threadIdx.x;
    const int i0  = blockIdx.x * 128;
    const int lr  = tid >> 1;
    const int lk  = (tid & 1) * 8;
    const int tx  = tid & 15;
    const int ty  = tid >> 4;

    float acc[8][8];
    #pragma unroll
    for (int i = 0; i < 8; i++)
        #pragma unroll
        for (int j = 0; j < 8; j++) acc[i][j] = 0.f;

    for (int k0 = 0; k0 < LDOUT; k0 += 16) {
        {
            int row = i0 + lr;
            #pragma unroll
            for (int j = 0; j < 8; j++) {
                int k = k0 + lk + j;
                float v = 0.f;
                if (row < M) {
                    if (k < DIMF) v = g_h[(size_t)row * DIMF + k];
                    else          v = sf[(size_t)sidx[row] * DIMF + (k - DIMF)];
                }
                As[lk + j][lr] = v;
            }
        }
        {
            #pragma unroll
            for (int j = 0; j < 8; j++) {
                int k = k0 + lk + j;
                Bs[lk + j][lr] = W[(size_t)lr * LDOUT + k];
            }
        }
        __syncthreads();
        #pragma unroll
        for (int kk = 0; kk < 16; kk++) {
            float4 a0 = *(const float4*)&As[kk][ty * 8];
            float4 a1 = *(const float4*)&As[kk][ty * 8 + 4];
            float4 b0 = *(const float4*)&Bs[kk][tx * 8];
            float4 b1 = *(const float4*)&Bs[kk][tx * 8 + 4];
            float ar[8] = {a0.x, a0.y, a0.z, a0.w, a1.x, a1.y, a1.z, a1.w};
            float br[8] = {b0.x, b0.y, b0.z, b0.w, b1.x, b1.y, b1.z, b1.w};
            #pragma unroll
            for (int i = 0; i < 8; i++)
                #pragma unroll
                for (int j = 0; j < 8; j++)
                    acc[i][j] += ar[i] * br[j];
        }
        __syncthreads();
    }
    #pragma unroll
    for (int i = 0; i < 8; i++) {
        int row = i0 + ty * 8 + i;
        if (row >= M) continue;
        #pragma unroll
        for (int j = 0; j < 8; j++) {
            int col = tx * 8 + j;
            g_rst[(size_t)row * DIMF + col] = fmaxf(acc[i][j] + bias[col], 0.f);
        }
    }
}

// ---------------- layernorm (warp per row) ----------------
__global__ __launch_bounds__(256)
void ln_kernel(const float* __restrict__ ln_g, const float* __restrict__ ln_b,
               float* __restrict__ out, int D) {
    int row = (blockIdx.x * blockDim.x + threadIdx.x) >> 5;
    int lane = threadIdx.x & 31;
    if (row >= D) return;

    float4 v = *(const float4*)&g_rst[(size_t)row * DIMF + lane * 4];
    float s  = v.x + v.y + v.z + v.w;
    float s2 = v.x * v.x + v.y * v.y + v.z * v.z + v.w * v.w;
    #pragma unroll
    for (int off = 16; off > 0; off >>= 1) {
        s  += __shfl_xor_sync(0xffffffffu, s,  off);
        s2 += __shfl_xor_sync(0xffffffffu, s2, off);
    }
    float mean = s * (1.f / DIMF);
    float var  = s2 * (1.f / DIMF) - mean * mean;
    float rstd = rsqrtf(var + LN_EPS);

    float4 g = *(const float4*)&ln_g[lane * 4];
    float4 b = *(const float4*)&ln_b[lane * 4];
    float4 o;
    o.x = (v.x - mean) * rstd * g.x + b.x;
    o.y = (v.y - mean) * rstd * g.y + b.y;
    o.z = (v.z - mean) * rstd * g.z + b.z;
    o.w = (v.w - mean) * rstd * g.w + b.w;
    *(float4*)&out[(size_t)row * DIMF + lane * 4] = o;
}

// ---------------- launcher ----------------
extern "C" void kernel_launch(void* const* d_in, const int* in_sizes, int n_in,
                              void* d_out, int out_size) {
    const float* src_feat = (const float*)d_in[0];
    const float* edge_f   = (const float*)d_in[1];
    const float* edge_dt  = (const float*)d_in[2];
    const float* time_w   = (const float*)d_in[3];
    const float* time_b   = (const float*)d_in[4];
    const float* wq_w     = (const float*)d_in[5];
    const float* wq_b     = (const float*)d_in[6];
    const float* wk_w     = (const float*)d_in[7];
    const float* wk_b     = (const float*)d_in[8];
    const float* wv_w     = (const float*)d_in[9];
    const float* wv_b     = (const float*)d_in[10];
    const float* wout_w   = (const float*)d_in[11];
    const float* wout_b   = (const float*)d_in[12];
    const float* ln_g     = (const float*)d_in[13];
    const float* ln_b     = (const float*)d_in[14];
    const int*   src_idx  = (const int*)d_in[15];   // JAX x64-disabled: int32
    const int*   edge_dst = (const int*)d_in[16];   // JAX x64-disabled: int32

    const int E = in_sizes[1] / DIMF;
    const int D = in_sizes[0] / DIMF - E;

    qb2_kernel<<<1, 128>>>(wq_w, wq_b, time_b);
    nstart_kernel<<<(D + 1 + 255) / 256, 256>>>(edge_dst, E, D);

    // Qd = gathered node feats @ wq[:, :128]^T + qb2
    gemm_q<<<(D + 127) / 128, 256>>>(wq_w, src_feat, src_idx, D);

    // tQ[d,h,:] = Wk_h^T Q_h[d]  (folds K projection into destinations)
    {
        int warps = 8 * ((D + 3) / 4);
        tq_kernel<<<(warps * 32 + 255) / 256, 256>>>(wk_w, wk_b, D);
    }

    // one-pass online-softmax attention; writes normalized xbar
    edge_kernel<<<(D + 3) / 4, 128>>>(src_feat, src_idx, edge_f, edge_dt,
                                      time_w, time_b, D, E);

    // h[d] = Wv_ext @ xbar[d]
    {
        int warps = 8 * ((D + 1) / 2);
        hproj_kernel<<<(warps * 32 + 255) / 256, 256>>>(wv_w, wv_b, D);
    }

    // output projection + ReLU
    gemm_out<<<(D + 127) / 128, 256>>>(wout_w, wout_b, src_feat, src_idx, D);

    ln_kernel<<<(D + 7) / 8, 256>>>(ln_g, ln_b, (float*)d_out, D);
}